// round 1
// baseline (speedup 1.0000x reference)
#include <cuda_runtime.h>

#define BB 16
#define NN 256
#define FF 64
#define DD 128
#define HH 4
#define DHH 32
#define DFF_ 512
#define LL 2
#define ROWS (BB*NN)     // 4096
#define PP (NN*(NN-1))   // 65280
#define EPSF 1e-5f

// ---------------- scratch (no allocation allowed) ----------------
__device__ float g_x[ROWS*DD];
__device__ float g_qkv[ROWS*3*DD];
__device__ float g_attn[ROWS*DD];
__device__ float g_ffn[ROWS*DFF_];
__device__ float g_A[ROWS*DD];
__device__ float g_Bm[ROWS*DD];

// ---------------- helpers ----------------
__device__ __forceinline__ float2 block_meanvar_128(float v) {
  __shared__ float rs[4], rs2[4];
  float s = v, s2 = v * v;
  #pragma unroll
  for (int o = 16; o; o >>= 1) {
    s  += __shfl_xor_sync(0xffffffffu, s,  o);
    s2 += __shfl_xor_sync(0xffffffffu, s2, o);
  }
  int w = threadIdx.x >> 5;
  if ((threadIdx.x & 31) == 0) { rs[w] = s; rs2[w] = s2; }
  __syncthreads();
  float S  = rs[0] + rs[1] + rs[2] + rs[3];
  float S2 = rs2[0] + rs2[1] + rs2[2] + rs2[3];
  float mu  = S * (1.f / 128.f);
  float var = S2 * (1.f / 128.f) - mu * mu;
  return make_float2(mu, rsqrtf(var + EPSF));
}

// ---------------- encoder: relu(agents@W+b) -> LN ----------------
__global__ void k_encoder(const float* __restrict__ agents, const float* __restrict__ w,
                          const float* __restrict__ b, const float* __restrict__ g,
                          const float* __restrict__ beta) {
  __shared__ float xs[FF];
  int row = blockIdx.x, t = threadIdx.x;
  if (t < FF) xs[t] = agents[row * FF + t];
  __syncthreads();
  float acc = b[t];
  #pragma unroll
  for (int f = 0; f < FF; f++) acc += xs[f] * w[f * DD + t];
  acc = fmaxf(acc, 0.f);
  float2 mv = block_meanvar_128(acc);
  g_x[row * DD + t] = (acc - mv.x) * mv.y * g[t] + beta[t];
}

// ---------------- generic row GEMM: y = (x @ W + b), optional relu ----------------
template <int DIN, int NOUT, bool RELU>
__global__ void k_rowmm(const float* __restrict__ x, const float* __restrict__ W,
                        const float* __restrict__ bias, float* __restrict__ y) {
  __shared__ float xs[DIN];
  int row = blockIdx.x, t = threadIdx.x;
  for (int i = t; i < DIN; i += NOUT) xs[i] = x[row * DIN + i];
  __syncthreads();
  float acc = bias[t];
  #pragma unroll 8
  for (int d = 0; d < DIN; d++) acc += xs[d] * W[d * NOUT + t];
  if (RELU) acc = fmaxf(acc, 0.f);
  y[row * NOUT + t] = acc;
}

// ---------------- attention: one block per (b,h), one thread per query ----------------
__global__ void k_attn(const float* __restrict__ qkv, float* __restrict__ out) {
  int bh = blockIdx.x;
  int b = bh / HH, h = bh % HH;
  int q = threadIdx.x;  // 0..255
  const int TK = 128;
  __shared__ float Ks[TK][DHH + 1], Vs[TK][DHH + 1];
  const float* base = qkv + (size_t)b * NN * (3 * DD);

  float qr[DHH];
  #pragma unroll
  for (int d = 0; d < DHH; d++) qr[d] = base[q * (3 * DD) + h * DHH + d];

  float m = -1e30f, l = 0.f, o[DHH];
  #pragma unroll
  for (int d = 0; d < DHH; d++) o[d] = 0.f;
  const float scale = 0.17677669529663687f;  // 1/sqrt(32)

  for (int k0 = 0; k0 < NN; k0 += TK) {
    __syncthreads();
    for (int idx = threadIdx.x; idx < TK * DHH; idx += NN) {
      int r = idx / DHH, d = idx % DHH;
      Ks[r][d] = base[(k0 + r) * (3 * DD) + DD     + h * DHH + d];
      Vs[r][d] = base[(k0 + r) * (3 * DD) + 2 * DD + h * DHH + d];
    }
    __syncthreads();
    for (int k = 0; k < TK; k++) {
      float s = 0.f;
      #pragma unroll
      for (int d = 0; d < DHH; d++) s += qr[d] * Ks[k][d];
      s *= scale;
      if (s > m) {
        float c = expf(m - s);
        l = l * c + 1.f;
        #pragma unroll
        for (int d = 0; d < DHH; d++) o[d] = o[d] * c + Vs[k][d];
        m = s;
      } else {
        float p = expf(s - m);
        l += p;
        #pragma unroll
        for (int d = 0; d < DHH; d++) o[d] += p * Vs[k][d];
      }
    }
  }
  float inv = 1.f / l;
  #pragma unroll
  for (int d = 0; d < DHH; d++)
    out[(size_t)(b * NN + q) * DD + h * DHH + d] = o[d] * inv;
}

// ---------------- projection + residual + LN (overwrites g_x) ----------------
template <int DIN>
__global__ void k_proj_res_ln(const float* __restrict__ inb, const float* __restrict__ W,
                              const float* __restrict__ bias, const float* __restrict__ g,
                              const float* __restrict__ beta) {
  __shared__ float s[DIN];
  int row = blockIdx.x, t = threadIdx.x;  // 128 threads
  for (int i = t; i < DIN; i += DD) s[i] = inb[row * DIN + i];
  __syncthreads();
  float acc = bias[t];
  #pragma unroll 8
  for (int d = 0; d < DIN; d++) acc += s[d] * W[d * DD + t];
  acc += g_x[row * DD + t];
  float2 mv = block_meanvar_128(acc);
  g_x[row * DD + t] = (acc - mv.x) * mv.y * g[t] + beta[t];
}

// ---------------- pair precompute: A = x@W1[:D]+b1, Bm = x@W1[D:] ----------------
__global__ void k_pairpre(const float* __restrict__ w1, const float* __restrict__ b1) {
  __shared__ float xs[DD];
  int row = blockIdx.x, t = threadIdx.x;  // 256 threads
  if (t < DD) xs[t] = g_x[row * DD + t];
  __syncthreads();
  int col = t & 127;
  const float* w = w1 + ((t < DD) ? 0 : DD * DD);
  float acc = (t < DD) ? b1[col] : 0.f;
  #pragma unroll 8
  for (int d = 0; d < DD; d++) acc += xs[d] * w[d * DD + col];
  if (t < DD) g_A[row * DD + col] = acc;
  else        g_Bm[row * DD + col] = acc;
}

// ---------------- pair kernel: out[b, i*255 + j'] = sum_d relu(A+B)*w2 + b2 ----------------
__global__ void k_pair(const float* __restrict__ w2, const float* __restrict__ b2,
                       float* __restrict__ out) {
  __shared__ float As[8][DD];
  __shared__ float Bs[64][DD + 1];
  __shared__ float w2s[DD];
  int b = blockIdx.y;
  int i0 = blockIdx.x * 8;
  int t = threadIdx.x;  // 256

  if (t < DD) w2s[t] = w2[t];
  for (int idx = t; idx < 8 * DD; idx += 256) {
    int li = idx >> 7, d = idx & 127;
    As[li][d] = g_A[(size_t)(b * NN + i0 + li) * DD + d];
  }
  float b2v = b2[0];
  int li = t >> 6;   // 0..3
  int jl = t & 63;   // 0..63
  float* outb = out + (size_t)b * PP;

  for (int j0 = 0; j0 < NN; j0 += 64) {
    __syncthreads();
    for (int idx = t; idx < 64 * DD; idx += 256) {
      int r = idx >> 7, d = idx & 127;
      Bs[r][d] = g_Bm[(size_t)(b * NN + j0 + r) * DD + d];
    }
    __syncthreads();
    int j = j0 + jl;
    int i_a = i0 + li, i_b = i0 + li + 4;
    float acc0 = 0.f, acc1 = 0.f;
    #pragma unroll 4
    for (int d = 0; d < DD; d++) {
      float bv = Bs[jl][d];
      float wv = w2s[d];
      acc0 += fmaxf(As[li][d] + bv, 0.f) * wv;
      acc1 += fmaxf(As[li + 4][d] + bv, 0.f) * wv;
    }
    if (j != i_a) outb[i_a * (NN - 1) + j - (j > i_a ? 1 : 0)] = acc0 + b2v;
    if (j != i_b) outb[i_b * (NN - 1) + j - (j > i_b ? 1 : 0)] = acc1 + b2v;
  }
}

// ---------------- host ----------------
extern "C" void kernel_launch(void* const* d_in, const int* in_sizes, int n_in,
                              void* d_out, int out_size) {
  const float* agents   = (const float*)d_in[0];
  const float* enc_w    = (const float*)d_in[1];
  const float* enc_b    = (const float*)d_in[2];
  const float* enc_g    = (const float*)d_in[3];
  const float* enc_beta = (const float*)d_in[4];
  const float* qkv_w    = (const float*)d_in[5];
  const float* qkv_b    = (const float*)d_in[6];
  const float* attn_ow  = (const float*)d_in[7];
  const float* attn_ob  = (const float*)d_in[8];
  const float* ln1_g    = (const float*)d_in[9];
  const float* ln1_b    = (const float*)d_in[10];
  const float* ffn_w1   = (const float*)d_in[11];
  const float* ffn_b1   = (const float*)d_in[12];
  const float* ffn_w2   = (const float*)d_in[13];
  const float* ffn_b2   = (const float*)d_in[14];
  const float* ln2_g    = (const float*)d_in[15];
  const float* ln2_b    = (const float*)d_in[16];
  const float* rel_w1   = (const float*)d_in[17];
  const float* rel_b1   = (const float*)d_in[18];
  const float* rel_w2   = (const float*)d_in[19];
  const float* rel_b2   = (const float*)d_in[20];
  float* out = (float*)d_out;

  float *px, *pqkv, *pattn, *pffn;
  cudaGetSymbolAddress((void**)&px,    g_x);
  cudaGetSymbolAddress((void**)&pqkv,  g_qkv);
  cudaGetSymbolAddress((void**)&pattn, g_attn);
  cudaGetSymbolAddress((void**)&pffn,  g_ffn);

  k_encoder<<<ROWS, DD>>>(agents, enc_w, enc_b, enc_g, enc_beta);

  for (int l = 0; l < LL; l++) {
    k_rowmm<DD, 3 * DD, false><<<ROWS, 3 * DD>>>(
        px, qkv_w + (size_t)l * DD * 3 * DD, qkv_b + (size_t)l * 3 * DD, pqkv);
    k_attn<<<BB * HH, NN>>>(pqkv, pattn);
    k_proj_res_ln<DD><<<ROWS, DD>>>(
        pattn, attn_ow + (size_t)l * DD * DD, attn_ob + (size_t)l * DD,
        ln1_g + (size_t)l * DD, ln1_b + (size_t)l * DD);
    k_rowmm<DD, DFF_, true><<<ROWS, DFF_>>>(
        px, ffn_w1 + (size_t)l * DD * DFF_, ffn_b1 + (size_t)l * DFF_, pffn);
    k_proj_res_ln<DFF_><<<ROWS, DD>>>(
        pffn, ffn_w2 + (size_t)l * DFF_ * DD, ffn_b2 + (size_t)l * DD,
        ln2_g + (size_t)l * DD, ln2_b + (size_t)l * DD);
  }

  k_pairpre<<<ROWS, 256>>>(rel_w1, rel_b1);
  dim3 pg(NN / 8, BB);
  k_pair<<<pg, 256>>>(rel_w2, rel_b2, out);
}

// round 2
// speedup vs baseline: 1.3147x; 1.3147x over previous
#include <cuda_runtime.h>

#define BB 16
#define NN 256
#define FF 64
#define DD 128
#define HH 4
#define DHH 32
#define DFF_ 512
#define LL 2
#define ROWS (BB*NN)     // 4096
#define PP (NN*(NN-1))   // 65280
#define EPSF 1e-5f

// ---------------- scratch (no allocation allowed) ----------------
__device__ float g_x[ROWS*DD];
__device__ float g_qkv[ROWS*3*DD];
__device__ float g_attn[ROWS*DD];
__device__ float g_ffn[ROWS*DFF_];
__device__ float g_A[ROWS*DD];
__device__ float g_Bm[ROWS*DD];

// ---------------- f32x2 packed helpers ----------------
typedef unsigned long long u64;

__device__ __forceinline__ u64 pack2(float x, float y) {
  u64 r; asm("mov.b64 %0, {%1, %2};" : "=l"(r) : "f"(x), "f"(y)); return r;
}
__device__ __forceinline__ float2 unpack2(u64 v) {
  float2 r; asm("mov.b64 {%0, %1}, %2;" : "=f"(r.x), "=f"(r.y) : "l"(v)); return r;
}
// d = a*b + d
__device__ __forceinline__ void ffma2(u64 &d, u64 a, u64 b) {
  asm("fma.rn.f32x2 %0, %1, %2, %0;" : "+l"(d) : "l"(a), "l"(b));
}
// o = a*b + c
__device__ __forceinline__ u64 ffma2_o(u64 a, u64 b, u64 c) {
  u64 o; asm("fma.rn.f32x2 %0, %1, %2, %3;" : "=l"(o) : "l"(a), "l"(b), "l"(c)); return o;
}

// ---------------- tiled GEMM: Y[M,NOUT] = X[M,KK] @ W[KK,NOUT] + epi ----------------
// EPI: 0 = +bias; 1 = +bias,relu; 2 = +bias,+res,LN; 3 = +bias,relu,LN; 4 = nothing
// BM = 16*TM, BN = 128, BK = 16, 256 threads, thread tile TM x 8.
template <int TM, int EPI>
__global__ void k_gemm(const float* __restrict__ X, int KK,
                       const float* __restrict__ W, int NOUT,
                       const float* __restrict__ bias, float* __restrict__ Y,
                       const float* __restrict__ res,
                       const float* __restrict__ g, const float* __restrict__ beta) {
  constexpr int BM = 16 * TM;
  __shared__ float As[16][BM];
  __shared__ float Bs[16][128];
  const int t = threadIdx.x;
  const int ty = t >> 4, tx = t & 15;
  const int bm0 = blockIdx.x * BM;
  const int bn0 = blockIdx.y * 128;
  const int col = bn0 + tx * 8;

  // acc init with bias
  u64 acc[TM][4];
  {
    u64 b0 = 0, b1 = 0, b2 = 0, b3 = 0;
    if (EPI != 4) {
      float4 v0 = *(const float4*)&bias[col];
      float4 v1 = *(const float4*)&bias[col + 4];
      b0 = pack2(v0.x, v0.y); b1 = pack2(v0.z, v0.w);
      b2 = pack2(v1.x, v1.y); b3 = pack2(v1.z, v1.w);
    }
    #pragma unroll
    for (int i = 0; i < TM; i++) { acc[i][0] = b0; acc[i][1] = b1; acc[i][2] = b2; acc[i][3] = b3; }
  }

  constexpr int TPR = 16 / TM;          // threads per A-row
  const int arow = t / TPR;             // 0..BM-1
  const int akq  = (t % TPR) * TM;      // k offset within tile

  for (int k0 = 0; k0 < KK; k0 += 16) {
    // load A tile (transposed into As[k][m])
    if (TM == 4) {
      float4 v = *(const float4*)&X[(size_t)(bm0 + arow) * KK + k0 + akq];
      As[akq + 0][arow] = v.x; As[akq + 1][arow] = v.y;
      As[akq + 2][arow] = v.z; As[akq + 3][arow] = v.w;
    } else {
      float2 v = *(const float2*)&X[(size_t)(bm0 + arow) * KK + k0 + akq];
      As[akq + 0][arow] = v.x; As[akq + 1][arow] = v.y;
    }
    // load B tile
    {
      const float* wp = &W[(size_t)(k0 + ty) * NOUT + col];
      *(float4*)&Bs[ty][tx * 8]     = *(const float4*)wp;
      *(float4*)&Bs[ty][tx * 8 + 4] = *(const float4*)(wp + 4);
    }
    __syncthreads();
    #pragma unroll
    for (int k = 0; k < 16; k++) {
      ulonglong2 bq0 = *(const ulonglong2*)&Bs[k][tx * 8];
      ulonglong2 bq1 = *(const ulonglong2*)&Bs[k][tx * 8 + 4];
      float a[TM];
      if (TM == 4) {
        float4 av = *(const float4*)&As[k][ty * 4];
        a[0] = av.x; a[1] = av.y; a[2] = av.z; a[3] = av.w;
      } else {
        float2 av = *(const float2*)&As[k][ty * 2];
        a[0] = av.x; a[1] = av.y;
      }
      #pragma unroll
      for (int i = 0; i < TM; i++) {
        u64 pa = pack2(a[i], a[i]);
        ffma2(acc[i][0], pa, bq0.x);
        ffma2(acc[i][1], pa, bq0.y);
        ffma2(acc[i][2], pa, bq1.x);
        ffma2(acc[i][3], pa, bq1.y);
      }
    }
    __syncthreads();
  }

  // epilogue
  #pragma unroll
  for (int i = 0; i < TM; i++) {
    int row = bm0 + ty * TM + i;
    float f[8];
    #pragma unroll
    for (int j = 0; j < 4; j++) {
      float2 u = unpack2(acc[i][j]);
      f[2 * j] = u.x; f[2 * j + 1] = u.y;
    }
    if (EPI == 1 || EPI == 3) {
      #pragma unroll
      for (int j = 0; j < 8; j++) f[j] = fmaxf(f[j], 0.f);
    }
    if (EPI == 2) {
      float4 r0 = *(const float4*)&res[(size_t)row * 128 + tx * 8];
      float4 r1 = *(const float4*)&res[(size_t)row * 128 + tx * 8 + 4];
      f[0] += r0.x; f[1] += r0.y; f[2] += r0.z; f[3] += r0.w;
      f[4] += r1.x; f[5] += r1.y; f[6] += r1.z; f[7] += r1.w;
    }
    if (EPI == 2 || EPI == 3) {
      float s = 0.f, s2 = 0.f;
      #pragma unroll
      for (int j = 0; j < 8; j++) { s += f[j]; s2 += f[j] * f[j]; }
      #pragma unroll
      for (int o = 8; o; o >>= 1) {
        s  += __shfl_xor_sync(0xffffffffu, s,  o);
        s2 += __shfl_xor_sync(0xffffffffu, s2, o);
      }
      float mu = s * (1.f / 128.f);
      float var = s2 * (1.f / 128.f) - mu * mu;
      float rstd = rsqrtf(var + EPSF);
      float4 g0 = *(const float4*)&g[col];
      float4 g1 = *(const float4*)&g[col + 4];
      float4 e0 = *(const float4*)&beta[col];
      float4 e1 = *(const float4*)&beta[col + 4];
      f[0] = (f[0] - mu) * rstd * g0.x + e0.x; f[1] = (f[1] - mu) * rstd * g0.y + e0.y;
      f[2] = (f[2] - mu) * rstd * g0.z + e0.z; f[3] = (f[3] - mu) * rstd * g0.w + e0.w;
      f[4] = (f[4] - mu) * rstd * g1.x + e1.x; f[5] = (f[5] - mu) * rstd * g1.y + e1.y;
      f[6] = (f[6] - mu) * rstd * g1.z + e1.z; f[7] = (f[7] - mu) * rstd * g1.w + e1.w;
    }
    float* yp = &Y[(size_t)row * NOUT + col];
    *(float4*)yp       = make_float4(f[0], f[1], f[2], f[3]);
    *(float4*)(yp + 4) = make_float4(f[4], f[5], f[6], f[7]);
  }
}

// ---------------- attention: one block per (b,h,qhalf), 128 threads ----------------
__global__ void k_attn(const float* __restrict__ qkv, float* __restrict__ out) {
  const int b = blockIdx.z, h = blockIdx.y;
  const int q = blockIdx.x * 128 + threadIdx.x;
  const int TK = 128;
  __shared__ float Ks[TK][DHH], Vs[TK][DHH];
  const float* base = qkv + (size_t)b * NN * (3 * DD);
  const int hoff = h * DHH;

  // load q row packed
  u64 qp[16];
  {
    const ulonglong2* qptr = (const ulonglong2*)(base + (size_t)q * (3 * DD) + hoff);
    #pragma unroll
    for (int i = 0; i < 8; i++) { ulonglong2 u = qptr[i]; qp[2 * i] = u.x; qp[2 * i + 1] = u.y; }
  }

  float m = -1e30f, l = 0.f;
  u64 op[16];
  #pragma unroll
  for (int i = 0; i < 16; i++) op[i] = 0ull;
  const float scale = 0.17677669529663687f;  // 1/sqrt(32)

  for (int k0 = 0; k0 < NN; k0 += TK) {
    __syncthreads();
    for (int c = threadIdx.x; c < TK * DHH / 4; c += 128) {
      int r = c >> 3, d4 = (c & 7) << 2;
      *(float4*)&Ks[r][d4] = *(const float4*)&base[(size_t)(k0 + r) * (3 * DD) + DD + hoff + d4];
      *(float4*)&Vs[r][d4] = *(const float4*)&base[(size_t)(k0 + r) * (3 * DD) + 2 * DD + hoff + d4];
    }
    __syncthreads();
    for (int k = 0; k < TK; k++) {
      const ulonglong2* kr = (const ulonglong2*)&Ks[k][0];
      u64 sp0 = 0, sp1 = 0, sp2 = 0, sp3 = 0;
      #pragma unroll
      for (int i = 0; i < 4; i++) {
        ulonglong2 ka = kr[2 * i], kb = kr[2 * i + 1];
        ffma2(sp0, qp[4 * i],     ka.x);
        ffma2(sp1, qp[4 * i + 1], ka.y);
        ffma2(sp2, qp[4 * i + 2], kb.x);
        ffma2(sp3, qp[4 * i + 3], kb.y);
      }
      float2 u0 = unpack2(sp0), u1 = unpack2(sp1), u2 = unpack2(sp2), u3 = unpack2(sp3);
      float s = ((u0.x + u0.y) + (u1.x + u1.y)) + ((u2.x + u2.y) + (u3.x + u3.y));
      s *= scale;
      const ulonglong2* vr = (const ulonglong2*)&Vs[k][0];
      if (s > m) {
        float c = __expf(m - s);
        m = s;
        l = l * c + 1.f;
        u64 cp = pack2(c, c);
        #pragma unroll
        for (int i = 0; i < 8; i++) {
          ulonglong2 vv = vr[i];
          op[2 * i]     = ffma2_o(op[2 * i],     cp, vv.x);
          op[2 * i + 1] = ffma2_o(op[2 * i + 1], cp, vv.y);
        }
      } else {
        float p = __expf(s - m);
        l += p;
        u64 pp = pack2(p, p);
        #pragma unroll
        for (int i = 0; i < 8; i++) {
          ulonglong2 vv = vr[i];
          ffma2(op[2 * i],     pp, vv.x);
          ffma2(op[2 * i + 1], pp, vv.y);
        }
      }
    }
  }
  float inv = 1.f / l;
  float* optr = out + (size_t)(b * NN + q) * DD + hoff;
  #pragma unroll
  for (int i = 0; i < 8; i++) {
    float2 a = unpack2(op[2 * i]), c = unpack2(op[2 * i + 1]);
    *(float4*)&optr[4 * i] = make_float4(a.x * inv, a.y * inv, c.x * inv, c.y * inv);
  }
}

// ---------------- pair kernel: out[b, i*255 + j'] = sum_d relu(A+B)*w2 + b2 ----------------
__global__ void k_pair(const float* __restrict__ w2, const float* __restrict__ b2,
                       float* __restrict__ out) {
  __shared__ float As[8][DD];
  __shared__ float Bs[64][DD + 1];
  __shared__ float w2s[DD];
  int b = blockIdx.y;
  int i0 = blockIdx.x * 8;
  int t = threadIdx.x;  // 256

  if (t < DD) w2s[t] = w2[t];
  for (int idx = t; idx < 8 * DD; idx += 256) {
    int li = idx >> 7, d = idx & 127;
    As[li][d] = g_A[(size_t)(b * NN + i0 + li) * DD + d];
  }
  float b2v = b2[0];
  int li = t >> 6;   // 0..3
  int jl = t & 63;   // 0..63
  float* outb = out + (size_t)b * PP;

  for (int j0 = 0; j0 < NN; j0 += 64) {
    __syncthreads();
    for (int idx = t; idx < 64 * DD; idx += 256) {
      int r = idx >> 7, d = idx & 127;
      Bs[r][d] = g_Bm[(size_t)(b * NN + j0 + r) * DD + d];
    }
    __syncthreads();
    int j = j0 + jl;
    int i_a = i0 + li, i_b = i0 + li + 4;
    float acc0 = 0.f, acc1 = 0.f;
    #pragma unroll 4
    for (int d = 0; d < DD; d++) {
      float bv = Bs[jl][d];
      float wv = w2s[d];
      acc0 += fmaxf(As[li][d] + bv, 0.f) * wv;
      acc1 += fmaxf(As[li + 4][d] + bv, 0.f) * wv;
    }
    if (j != i_a) outb[i_a * (NN - 1) + j - (j > i_a ? 1 : 0)] = acc0 + b2v;
    if (j != i_b) outb[i_b * (NN - 1) + j - (j > i_b ? 1 : 0)] = acc1 + b2v;
  }
}

// ---------------- host ----------------
extern "C" void kernel_launch(void* const* d_in, const int* in_sizes, int n_in,
                              void* d_out, int out_size) {
  const float* agents   = (const float*)d_in[0];
  const float* enc_w    = (const float*)d_in[1];
  const float* enc_b    = (const float*)d_in[2];
  const float* enc_g    = (const float*)d_in[3];
  const float* enc_beta = (const float*)d_in[4];
  const float* qkv_w    = (const float*)d_in[5];
  const float* qkv_b    = (const float*)d_in[6];
  const float* attn_ow  = (const float*)d_in[7];
  const float* attn_ob  = (const float*)d_in[8];
  const float* ln1_g    = (const float*)d_in[9];
  const float* ln1_b    = (const float*)d_in[10];
  const float* ffn_w1   = (const float*)d_in[11];
  const float* ffn_b1   = (const float*)d_in[12];
  const float* ffn_w2   = (const float*)d_in[13];
  const float* ffn_b2   = (const float*)d_in[14];
  const float* ln2_g    = (const float*)d_in[15];
  const float* ln2_b    = (const float*)d_in[16];
  const float* rel_w1   = (const float*)d_in[17];
  const float* rel_b1   = (const float*)d_in[18];
  const float* rel_w2   = (const float*)d_in[19];
  const float* rel_b2   = (const float*)d_in[20];
  float* out = (float*)d_out;

  float *px, *pqkv, *pattn, *pffn, *pA, *pBm;
  cudaGetSymbolAddress((void**)&px,    g_x);
  cudaGetSymbolAddress((void**)&pqkv,  g_qkv);
  cudaGetSymbolAddress((void**)&pattn, g_attn);
  cudaGetSymbolAddress((void**)&pffn,  g_ffn);
  cudaGetSymbolAddress((void**)&pA,    g_A);
  cudaGetSymbolAddress((void**)&pBm,   g_Bm);

  // encoder: relu(agents @ enc_w + b) -> LN
  k_gemm<2, 3><<<dim3(ROWS / 32, 1), 256>>>(agents, FF, enc_w, DD, enc_b, px,
                                            nullptr, enc_g, enc_beta);

  for (int l = 0; l < LL; l++) {
    k_gemm<4, 0><<<dim3(ROWS / 64, 3), 256>>>(px, DD, qkv_w + (size_t)l * DD * 3 * DD,
                                              3 * DD, qkv_b + (size_t)l * 3 * DD, pqkv,
                                              nullptr, nullptr, nullptr);
    k_attn<<<dim3(2, HH, BB), 128>>>(pqkv, pattn);
    k_gemm<2, 2><<<dim3(ROWS / 32, 1), 256>>>(pattn, DD, attn_ow + (size_t)l * DD * DD,
                                              DD, attn_ob + (size_t)l * DD, px,
                                              px, ln1_g + (size_t)l * DD, ln1_b + (size_t)l * DD);
    k_gemm<4, 1><<<dim3(ROWS / 64, 4), 256>>>(px, DD, ffn_w1 + (size_t)l * DD * DFF_,
                                              DFF_, ffn_b1 + (size_t)l * DFF_, pffn,
                                              nullptr, nullptr, nullptr);
    k_gemm<2, 2><<<dim3(ROWS / 32, 1), 256>>>(pffn, DFF_, ffn_w2 + (size_t)l * DFF_ * DD,
                                              DD, ffn_b2 + (size_t)l * DD, px,
                                              px, ln2_g + (size_t)l * DD, ln2_b + (size_t)l * DD);
  }

  // pair precompute: A = x@W1[:D]+b1 ; Bm = x@W1[D:]
  k_gemm<4, 0><<<dim3(ROWS / 64, 1), 256>>>(px, DD, rel_w1, DD, rel_b1, pA,
                                            nullptr, nullptr, nullptr);
  k_gemm<4, 4><<<dim3(ROWS / 64, 1), 256>>>(px, DD, rel_w1 + DD * DD, DD, nullptr, pBm,
                                            nullptr, nullptr, nullptr);

  dim3 pg(NN / 8, BB);
  k_pair<<<pg, 256>>>(rel_w2, rel_b2, out);
}

// round 3
// speedup vs baseline: 1.3349x; 1.0153x over previous
#include <cuda_runtime.h>

#define BB 16
#define NN 256
#define FF 64
#define DD 128
#define HH 4
#define DHH 32
#define DFF_ 512
#define LL 2
#define ROWS (BB*NN)     // 4096
#define PP (NN*(NN-1))   // 65280
#define EPSF 1e-5f
#define SPLITS 4
#define BHQ (BB*HH*NN)   // 16384

// ---------------- scratch ----------------
__device__ float g_x[ROWS*DD];
__device__ float g_qkv[ROWS*3*DD];
__device__ float g_attn[ROWS*DD];
__device__ float g_ffn[ROWS*DFF_];    // also attention po scratch (SPLITS*BHQ*32 = 2097152 exact)
__device__ float g_A[ROWS*DD];        // also attention ml scratch (SPLITS*BHQ*2 = 131072)
__device__ float g_Bm[ROWS*DD];

typedef unsigned long long u64;

__device__ __forceinline__ u64 pack2(float x, float y) {
  u64 r; asm("mov.b64 %0, {%1, %2};" : "=l"(r) : "f"(x), "f"(y)); return r;
}
__device__ __forceinline__ float2 unpack2(u64 v) {
  float2 r; asm("mov.b64 {%0, %1}, %2;" : "=f"(r.x), "=f"(r.y) : "l"(v)); return r;
}
__device__ __forceinline__ void ffma2(u64 &d, u64 a, u64 b) {
  asm("fma.rn.f32x2 %0, %1, %2, %0;" : "+l"(d) : "l"(a), "l"(b));
}
__device__ __forceinline__ u64 ffma2_o(u64 a, u64 b, u64 c) {
  u64 o; asm("fma.rn.f32x2 %0, %1, %2, %3;" : "=l"(o) : "l"(a), "l"(b), "l"(c)); return o;
}

// ================ GEMM A: BM=32, BN=64, BK=32, 128 threads, TM=4 x TN=4 ================
// EPI: 0 = +bias ; 1 = +bias,relu ; 5 = pairpre dual (blockIdx.z selects W half / output)
template <int EPI>
__global__ void k_gemmA(const float* __restrict__ X, int KK,
                        const float* __restrict__ W, int NOUT,
                        const float* __restrict__ bias,
                        float* __restrict__ Y, float* __restrict__ Y2) {
  __shared__ u64  As2[2][32][33];
  __shared__ float Bs[2][32][64];
  const int t  = threadIdx.x;
  const int tx = t & 15, ty = t >> 4;
  const int bm0 = blockIdx.x * 32, bn0 = blockIdx.y * 64;
  const int c0 = tx * 4, r0 = ty * 4;
  const int am = t >> 2, akq = (t & 3) * 8;
  const int bkr = t >> 2, bcq = (t & 3) * 16;

  if (EPI == 5) {
    if (blockIdx.z) { W += (size_t)KK * NOUT; Y = Y2; bias = nullptr; }
  }

  u64 acc[4][2];
  {
    u64 i0 = 0, i1 = 0;
    if (EPI != 5 || bias) {
      if (bias) {
        float4 bv = *(const float4*)&bias[bn0 + c0];
        i0 = pack2(bv.x, bv.y); i1 = pack2(bv.z, bv.w);
      }
    }
    #pragma unroll
    for (int i = 0; i < 4; i++) { acc[i][0] = i0; acc[i][1] = i1; }
  }

  const float* Xp = X + (size_t)(bm0 + am) * KK + akq;
  const float* Wp = W + (size_t)bkr * NOUT + bn0 + bcq;
  const int NT = KK >> 5;

  float4 a0 = *(const float4*)Xp;
  float4 a1 = *(const float4*)(Xp + 4);
  float4 b0 = *(const float4*)Wp;
  float4 b1 = *(const float4*)(Wp + 4);
  float4 b2 = *(const float4*)(Wp + 8);
  float4 b3 = *(const float4*)(Wp + 12);
  {
    As2[0][akq + 0][am] = pack2(a0.x, a0.x);
    As2[0][akq + 1][am] = pack2(a0.y, a0.y);
    As2[0][akq + 2][am] = pack2(a0.z, a0.z);
    As2[0][akq + 3][am] = pack2(a0.w, a0.w);
    As2[0][akq + 4][am] = pack2(a1.x, a1.x);
    As2[0][akq + 5][am] = pack2(a1.y, a1.y);
    As2[0][akq + 6][am] = pack2(a1.z, a1.z);
    As2[0][akq + 7][am] = pack2(a1.w, a1.w);
    *(float4*)&Bs[0][bkr][bcq]      = b0;
    *(float4*)&Bs[0][bkr][bcq + 4]  = b1;
    *(float4*)&Bs[0][bkr][bcq + 8]  = b2;
    *(float4*)&Bs[0][bkr][bcq + 12] = b3;
  }
  __syncthreads();

  for (int it = 0; it < NT; it++) {
    const int buf = it & 1;
    if (it + 1 < NT) {
      const float* xp = Xp + (it + 1) * 32;
      a0 = *(const float4*)xp; a1 = *(const float4*)(xp + 4);
      const float* wp = Wp + (size_t)(it + 1) * 32 * NOUT;
      b0 = *(const float4*)wp;        b1 = *(const float4*)(wp + 4);
      b2 = *(const float4*)(wp + 8);  b3 = *(const float4*)(wp + 12);
    }
    #pragma unroll
    for (int k = 0; k < 32; k++) {
      ulonglong2 bv = *(const ulonglong2*)&Bs[buf][k][c0];
      u64 av0 = As2[buf][k][r0 + 0];
      u64 av1 = As2[buf][k][r0 + 1];
      u64 av2 = As2[buf][k][r0 + 2];
      u64 av3 = As2[buf][k][r0 + 3];
      ffma2(acc[0][0], av0, bv.x); ffma2(acc[0][1], av0, bv.y);
      ffma2(acc[1][0], av1, bv.x); ffma2(acc[1][1], av1, bv.y);
      ffma2(acc[2][0], av2, bv.x); ffma2(acc[2][1], av2, bv.y);
      ffma2(acc[3][0], av3, bv.x); ffma2(acc[3][1], av3, bv.y);
    }
    if (it + 1 < NT) {
      const int nb = buf ^ 1;
      As2[nb][akq + 0][am] = pack2(a0.x, a0.x);
      As2[nb][akq + 1][am] = pack2(a0.y, a0.y);
      As2[nb][akq + 2][am] = pack2(a0.z, a0.z);
      As2[nb][akq + 3][am] = pack2(a0.w, a0.w);
      As2[nb][akq + 4][am] = pack2(a1.x, a1.x);
      As2[nb][akq + 5][am] = pack2(a1.y, a1.y);
      As2[nb][akq + 6][am] = pack2(a1.z, a1.z);
      As2[nb][akq + 7][am] = pack2(a1.w, a1.w);
      *(float4*)&Bs[nb][bkr][bcq]      = b0;
      *(float4*)&Bs[nb][bkr][bcq + 4]  = b1;
      *(float4*)&Bs[nb][bkr][bcq + 8]  = b2;
      *(float4*)&Bs[nb][bkr][bcq + 12] = b3;
    }
    __syncthreads();
  }

  #pragma unroll
  for (int i = 0; i < 4; i++) {
    float2 u0 = unpack2(acc[i][0]), u1 = unpack2(acc[i][1]);
    float4 f = make_float4(u0.x, u0.y, u1.x, u1.y);
    if (EPI == 1) {
      f.x = fmaxf(f.x, 0.f); f.y = fmaxf(f.y, 0.f);
      f.z = fmaxf(f.z, 0.f); f.w = fmaxf(f.w, 0.f);
    }
    *(float4*)&Y[(size_t)(bm0 + r0 + i) * NOUT + bn0 + c0] = f;
  }
}

// ================ GEMM B: BM=16, BN=128 (full row), BK=32, 128 threads, TM=2 x TN=8, fused LN ================
// EPI: 2 = +bias, +res, LN ; 3 = +bias, relu, LN
template <int EPI>
__global__ void k_gemmB(const float* __restrict__ X, int KK,
                        const float* __restrict__ W,
                        const float* __restrict__ bias,
                        float* __restrict__ Y,
                        const float* __restrict__ res,
                        const float* __restrict__ g, const float* __restrict__ beta) {
  __shared__ u64  As2[2][32][17];
  __shared__ float Bs[2][32][128];
  const int t  = threadIdx.x;
  const int tx = t & 15, ty = t >> 4;
  const int bm0 = blockIdx.x * 16;
  const int c0 = tx * 8, r0 = ty * 2;
  const int am = t >> 3, akq = (t & 7) * 4;
  const int bkr = t >> 2, bcq = (t & 3) * 32;

  u64 acc[2][4];
  {
    float4 bv0 = *(const float4*)&bias[c0];
    float4 bv1 = *(const float4*)&bias[c0 + 4];
    u64 i0 = pack2(bv0.x, bv0.y), i1 = pack2(bv0.z, bv0.w);
    u64 i2 = pack2(bv1.x, bv1.y), i3 = pack2(bv1.z, bv1.w);
    #pragma unroll
    for (int i = 0; i < 2; i++) { acc[i][0]=i0; acc[i][1]=i1; acc[i][2]=i2; acc[i][3]=i3; }
  }

  const float* Xp = X + (size_t)(bm0 + am) * KK + akq;
  const float* Wp = W + (size_t)bkr * 128 + bcq;
  const int NT = KK >> 5;

  float4 a0 = *(const float4*)Xp;
  float4 bb[8];
  #pragma unroll
  for (int j = 0; j < 8; j++) bb[j] = *(const float4*)(Wp + 4 * j);
  {
    As2[0][akq + 0][am] = pack2(a0.x, a0.x);
    As2[0][akq + 1][am] = pack2(a0.y, a0.y);
    As2[0][akq + 2][am] = pack2(a0.z, a0.z);
    As2[0][akq + 3][am] = pack2(a0.w, a0.w);
    #pragma unroll
    for (int j = 0; j < 8; j++) *(float4*)&Bs[0][bkr][bcq + 4 * j] = bb[j];
  }
  __syncthreads();

  for (int it = 0; it < NT; it++) {
    const int buf = it & 1;
    if (it + 1 < NT) {
      a0 = *(const float4*)(Xp + (it + 1) * 32);
      const float* wp = Wp + (size_t)(it + 1) * 32 * 128;
      #pragma unroll
      for (int j = 0; j < 8; j++) bb[j] = *(const float4*)(wp + 4 * j);
    }
    #pragma unroll
    for (int k = 0; k < 32; k++) {
      ulonglong2 bv0 = *(const ulonglong2*)&Bs[buf][k][c0];
      ulonglong2 bv1 = *(const ulonglong2*)&Bs[buf][k][c0 + 4];
      u64 av0 = As2[buf][k][r0 + 0];
      u64 av1 = As2[buf][k][r0 + 1];
      ffma2(acc[0][0], av0, bv0.x); ffma2(acc[0][1], av0, bv0.y);
      ffma2(acc[0][2], av0, bv1.x); ffma2(acc[0][3], av0, bv1.y);
      ffma2(acc[1][0], av1, bv0.x); ffma2(acc[1][1], av1, bv0.y);
      ffma2(acc[1][2], av1, bv1.x); ffma2(acc[1][3], av1, bv1.y);
    }
    if (it + 1 < NT) {
      const int nb = buf ^ 1;
      As2[nb][akq + 0][am] = pack2(a0.x, a0.x);
      As2[nb][akq + 1][am] = pack2(a0.y, a0.y);
      As2[nb][akq + 2][am] = pack2(a0.z, a0.z);
      As2[nb][akq + 3][am] = pack2(a0.w, a0.w);
      #pragma unroll
      for (int j = 0; j < 8; j++) *(float4*)&Bs[nb][bkr][bcq + 4 * j] = bb[j];
    }
    __syncthreads();
  }

  #pragma unroll
  for (int i = 0; i < 2; i++) {
    const int row = bm0 + r0 + i;
    float f[8];
    #pragma unroll
    for (int j = 0; j < 4; j++) {
      float2 u = unpack2(acc[i][j]);
      f[2 * j] = u.x; f[2 * j + 1] = u.y;
    }
    if (EPI == 3) {
      #pragma unroll
      for (int j = 0; j < 8; j++) f[j] = fmaxf(f[j], 0.f);
    }
    if (EPI == 2) {
      float4 r0v = *(const float4*)&res[(size_t)row * DD + c0];
      float4 r1v = *(const float4*)&res[(size_t)row * DD + c0 + 4];
      f[0] += r0v.x; f[1] += r0v.y; f[2] += r0v.z; f[3] += r0v.w;
      f[4] += r1v.x; f[5] += r1v.y; f[6] += r1v.z; f[7] += r1v.w;
    }
    float s = 0.f, s2 = 0.f;
    #pragma unroll
    for (int j = 0; j < 8; j++) { s += f[j]; s2 += f[j] * f[j]; }
    #pragma unroll
    for (int o = 8; o; o >>= 1) {
      s  += __shfl_xor_sync(0xffffffffu, s,  o);
      s2 += __shfl_xor_sync(0xffffffffu, s2, o);
    }
    float mu = s * (1.f / 128.f);
    float var = s2 * (1.f / 128.f) - mu * mu;
    float rstd = rsqrtf(var + EPSF);
    float4 g0 = *(const float4*)&g[c0];
    float4 g1 = *(const float4*)&g[c0 + 4];
    float4 e0 = *(const float4*)&beta[c0];
    float4 e1 = *(const float4*)&beta[c0 + 4];
    float o0 = (f[0] - mu) * rstd * g0.x + e0.x;
    float o1 = (f[1] - mu) * rstd * g0.y + e0.y;
    float o2 = (f[2] - mu) * rstd * g0.z + e0.z;
    float o3 = (f[3] - mu) * rstd * g0.w + e0.w;
    float o4 = (f[4] - mu) * rstd * g1.x + e1.x;
    float o5 = (f[5] - mu) * rstd * g1.y + e1.y;
    float o6 = (f[6] - mu) * rstd * g1.z + e1.z;
    float o7 = (f[7] - mu) * rstd * g1.w + e1.w;
    float* yp = &Y[(size_t)row * DD + c0];
    *(float4*)yp       = make_float4(o0, o1, o2, o3);
    *(float4*)(yp + 4) = make_float4(o4, o5, o6, o7);
  }
}

// ================ attention: split-K partials ================
__global__ void k_attn_part(const float* __restrict__ qkv,
                            float* __restrict__ po, float* __restrict__ ml) {
  const int split = blockIdx.x, h = blockIdx.y, b = blockIdx.z;
  const int q = threadIdx.x;  // 256
  __shared__ float Ks[64][DHH], Vs[64][DHH];
  const float* base = qkv + (size_t)b * NN * (3 * DD);
  const int hoff = h * DHH;
  const int kbase = split * 64;

  for (int c = threadIdx.x; c < 64 * DHH / 4; c += 256) {
    int r = c >> 3, d4 = (c & 7) << 2;
    *(float4*)&Ks[r][d4] = *(const float4*)&base[(size_t)(kbase + r) * (3 * DD) + DD     + hoff + d4];
    *(float4*)&Vs[r][d4] = *(const float4*)&base[(size_t)(kbase + r) * (3 * DD) + 2 * DD + hoff + d4];
  }
  u64 qp[16];
  {
    const ulonglong2* qptr = (const ulonglong2*)(base + (size_t)q * (3 * DD) + hoff);
    #pragma unroll
    for (int i = 0; i < 8; i++) { ulonglong2 u = qptr[i]; qp[2*i] = u.x; qp[2*i+1] = u.y; }
  }
  __syncthreads();

  float m = -1e30f, l = 0.f;
  u64 op[16];
  #pragma unroll
  for (int i = 0; i < 16; i++) op[i] = 0ull;
  const float scale = 0.17677669529663687f;

  for (int k = 0; k < 64; k++) {
    const ulonglong2* kr = (const ulonglong2*)&Ks[k][0];
    u64 sp0 = 0, sp1 = 0, sp2 = 0, sp3 = 0;
    #pragma unroll
    for (int i = 0; i < 4; i++) {
      ulonglong2 ka = kr[2*i], kb = kr[2*i+1];
      ffma2(sp0, qp[4*i],     ka.x);
      ffma2(sp1, qp[4*i + 1], ka.y);
      ffma2(sp2, qp[4*i + 2], kb.x);
      ffma2(sp3, qp[4*i + 3], kb.y);
    }
    float2 u0 = unpack2(sp0), u1 = unpack2(sp1), u2 = unpack2(sp2), u3 = unpack2(sp3);
    float s = ((u0.x + u0.y) + (u1.x + u1.y)) + ((u2.x + u2.y) + (u3.x + u3.y));
    s *= scale;
    const ulonglong2* vr = (const ulonglong2*)&Vs[k][0];
    if (s > m) {
      float c = __expf(m - s);
      m = s;
      l = l * c + 1.f;
      u64 cp = pack2(c, c);
      #pragma unroll
      for (int i = 0; i < 8; i++) {
        ulonglong2 vv = vr[i];
        op[2*i]     = ffma2_o(op[2*i],     cp, vv.x);
        op[2*i + 1] = ffma2_o(op[2*i + 1], cp, vv.y);
      }
    } else {
      float p = __expf(s - m);
      l += p;
      u64 pp = pack2(p, p);
      #pragma unroll
      for (int i = 0; i < 8; i++) {
        ulonglong2 vv = vr[i];
        ffma2(op[2*i],     pp, vv.x);
        ffma2(op[2*i + 1], pp, vv.y);
      }
    }
  }

  const int bhq = (b * HH + h) * NN + q;
  float* pop = po + ((size_t)split * BHQ + bhq) * 32;
  #pragma unroll
  for (int i = 0; i < 8; i++) {
    float2 a = unpack2(op[2*i]), c = unpack2(op[2*i + 1]);
    *(float4*)&pop[4*i] = make_float4(a.x, a.y, c.x, c.y);
  }
  *(float2*)&ml[((size_t)split * BHQ + bhq) * 2] = make_float2(m, l);
}

__global__ void k_attn_comb(const float* __restrict__ po, const float* __restrict__ ml,
                            float* __restrict__ out) {
  const int tid = blockIdx.x * 256 + threadIdx.x;  // BHQ*8 = 131072
  const int bhq = tid >> 3, dq = (tid & 7) << 2;
  float mv[SPLITS], lv[SPLITS];
  float M = -1e30f;
  #pragma unroll
  for (int s = 0; s < SPLITS; s++) {
    float2 p = *(const float2*)&ml[((size_t)s * BHQ + bhq) * 2];
    mv[s] = p.x; lv[s] = p.y;
    M = fmaxf(M, p.x);
  }
  float w[SPLITS], L = 0.f;
  #pragma unroll
  for (int s = 0; s < SPLITS; s++) { w[s] = __expf(mv[s] - M); L += w[s] * lv[s]; }
  const float inv = 1.f / L;
  float ox = 0.f, oy = 0.f, oz = 0.f, ow = 0.f;
  #pragma unroll
  for (int s = 0; s < SPLITS; s++) {
    float4 p = *(const float4*)&po[((size_t)s * BHQ + bhq) * 32 + dq];
    ox += w[s] * p.x; oy += w[s] * p.y; oz += w[s] * p.z; ow += w[s] * p.w;
  }
  const int b = bhq >> 10, h = (bhq >> 8) & 3, q = bhq & 255;
  *(float4*)&out[(size_t)((b << 8) + q) * DD + h * DHH + dq] =
      make_float4(ox * inv, oy * inv, oz * inv, ow * inv);
}

// ================ pair kernel ================
__global__ void k_pair(const float* __restrict__ w2, const float* __restrict__ b2,
                       float* __restrict__ out) {
  __shared__ float As[8][DD];
  __shared__ float Bs[64][DD + 1];
  __shared__ float w2s[DD];
  int b = blockIdx.y;
  int i0 = blockIdx.x * 8;
  int t = threadIdx.x;  // 256

  if (t < DD) w2s[t] = w2[t];
  for (int idx = t; idx < 8 * DD; idx += 256) {
    int li = idx >> 7, d = idx & 127;
    As[li][d] = g_A[(size_t)(b * NN + i0 + li) * DD + d];
  }
  float b2v = b2[0];
  int li = t >> 6;
  int jl = t & 63;
  float* outb = out + (size_t)b * PP;

  for (int j0 = 0; j0 < NN; j0 += 64) {
    __syncthreads();
    for (int idx = t; idx < 64 * DD; idx += 256) {
      int r = idx >> 7, d = idx & 127;
      Bs[r][d] = g_Bm[(size_t)(b * NN + j0 + r) * DD + d];
    }
    __syncthreads();
    int j = j0 + jl;
    int i_a = i0 + li, i_b = i0 + li + 4;
    float acc0 = 0.f, acc1 = 0.f;
    #pragma unroll 4
    for (int d = 0; d < DD; d++) {
      float bv = Bs[jl][d];
      float wv = w2s[d];
      acc0 += fmaxf(As[li][d] + bv, 0.f) * wv;
      acc1 += fmaxf(As[li + 4][d] + bv, 0.f) * wv;
    }
    if (j != i_a) outb[i_a * (NN - 1) + j - (j > i_a ? 1 : 0)] = acc0 + b2v;
    if (j != i_b) outb[i_b * (NN - 1) + j - (j > i_b ? 1 : 0)] = acc1 + b2v;
  }
}

// ================ host ================
extern "C" void kernel_launch(void* const* d_in, const int* in_sizes, int n_in,
                              void* d_out, int out_size) {
  const float* agents   = (const float*)d_in[0];
  const float* enc_w    = (const float*)d_in[1];
  const float* enc_b    = (const float*)d_in[2];
  const float* enc_g    = (const float*)d_in[3];
  const float* enc_beta = (const float*)d_in[4];
  const float* qkv_w    = (const float*)d_in[5];
  const float* qkv_b    = (const float*)d_in[6];
  const float* attn_ow  = (const float*)d_in[7];
  const float* attn_ob  = (const float*)d_in[8];
  const float* ln1_g    = (const float*)d_in[9];
  const float* ln1_b    = (const float*)d_in[10];
  const float* ffn_w1   = (const float*)d_in[11];
  const float* ffn_b1   = (const float*)d_in[12];
  const float* ffn_w2   = (const float*)d_in[13];
  const float* ffn_b2   = (const float*)d_in[14];
  const float* ln2_g    = (const float*)d_in[15];
  const float* ln2_b    = (const float*)d_in[16];
  const float* rel_w1   = (const float*)d_in[17];
  const float* rel_b1   = (const float*)d_in[18];
  const float* rel_w2   = (const float*)d_in[19];
  const float* rel_b2   = (const float*)d_in[20];
  float* out = (float*)d_out;

  float *px, *pqkv, *pattn, *pffn, *pA, *pBm;
  cudaGetSymbolAddress((void**)&px,    g_x);
  cudaGetSymbolAddress((void**)&pqkv,  g_qkv);
  cudaGetSymbolAddress((void**)&pattn, g_attn);
  cudaGetSymbolAddress((void**)&pffn,  g_ffn);
  cudaGetSymbolAddress((void**)&pA,    g_A);
  cudaGetSymbolAddress((void**)&pBm,   g_Bm);

  // encoder: relu(agents @ enc_w + b) -> LN   (K=64, N=128)
  k_gemmB<3><<<ROWS / 16, 128>>>(agents, FF, enc_w, enc_b, px, nullptr, enc_g, enc_beta);

  for (int l = 0; l < LL; l++) {
    k_gemmA<0><<<dim3(ROWS / 32, 6), 128>>>(px, DD, qkv_w + (size_t)l * DD * 3 * DD,
                                            3 * DD, qkv_b + (size_t)l * 3 * DD, pqkv, nullptr);
    k_attn_part<<<dim3(SPLITS, HH, BB), 256>>>(pqkv, pffn, pA);
    k_attn_comb<<<BHQ * 8 / 256, 256>>>(pffn, pA, pattn);
    k_gemmB<2><<<ROWS / 16, 128>>>(pattn, DD, attn_ow + (size_t)l * DD * DD,
                                   attn_ob + (size_t)l * DD, px, px,
                                   ln1_g + (size_t)l * DD, ln1_b + (size_t)l * DD);
    k_gemmA<1><<<dim3(ROWS / 32, 8), 128>>>(px, DD, ffn_w1 + (size_t)l * DD * DFF_,
                                            DFF_, ffn_b1 + (size_t)l * DFF_, pffn, nullptr);
    k_gemmB<2><<<ROWS / 16, 128>>>(pffn, DFF_, ffn_w2 + (size_t)l * DFF_ * DD,
                                   ffn_b2 + (size_t)l * DD, px, px,
                                   ln2_g + (size_t)l * DD, ln2_b + (size_t)l * DD);
  }

  // pair precompute: A = x@W1[:D]+b1 ; Bm = x@W1[D:]   (fused, blockIdx.z selects half)
  k_gemmA<5><<<dim3(ROWS / 32, 2, 2), 128>>>(px, DD, rel_w1, DD, rel_b1, pA, pBm);

  dim3 pg(NN / 8, BB);
  k_pair<<<pg, 256>>>(rel_w2, rel_b2, out);
}

// round 4
// speedup vs baseline: 2.0192x; 1.5126x over previous
#include <cuda_runtime.h>

#define BB 16
#define NN 256
#define FF 64
#define DD 128
#define HH 4
#define DHH 32
#define DFF_ 512
#define LL 2
#define ROWS (BB*NN)     // 4096
#define PP (NN*(NN-1))   // 65280
#define EPSF 1e-5f
#define SPLITS 2
#define BHQ (BB*HH*NN)   // 16384

// ---------------- scratch ----------------
__device__ float g_x[ROWS*DD];
__device__ float g_qkv[ROWS*3*DD];
__device__ float g_attn[ROWS*DD];
__device__ float g_ffn[ROWS*DFF_];    // also attention po scratch (SPLITS*BHQ*32 = 1048576 <= 2097152)
__device__ float g_A[ROWS*DD];        // also attention ml scratch (SPLITS*BHQ*2 = 65536 <= 524288)
__device__ float g_Bm[ROWS*DD];

typedef unsigned long long u64;

__device__ __forceinline__ u64 pack2(float x, float y) {
  u64 r; asm("mov.b64 %0, {%1, %2};" : "=l"(r) : "f"(x), "f"(y)); return r;
}
__device__ __forceinline__ float2 unpack2(u64 v) {
  float2 r; asm("mov.b64 {%0, %1}, %2;" : "=f"(r.x), "=f"(r.y) : "l"(v)); return r;
}
__device__ __forceinline__ void ffma2(u64 &d, u64 a, u64 b) {
  asm("fma.rn.f32x2 %0, %1, %2, %0;" : "+l"(d) : "l"(a), "l"(b));
}
__device__ __forceinline__ u64 ffma2_o(u64 a, u64 b, u64 c) {
  u64 o; asm("fma.rn.f32x2 %0, %1, %2, %3;" : "=l"(o) : "l"(a), "l"(b), "l"(c)); return o;
}
__device__ __forceinline__ u64 add2(u64 a, u64 b) {
  u64 o; asm("add.rn.f32x2 %0, %1, %2;" : "=l"(o) : "l"(a), "l"(b)); return o;
}
__device__ __forceinline__ u64 relu2(u64 v) {
  float2 f = unpack2(v);
  return pack2(fmaxf(f.x, 0.f), fmaxf(f.y, 0.f));
}

// ================ GEMM A: BM=64, BN=128, BK=16, 128 threads, 8x8 thread tile ================
// EPI: 0 = +bias ; 1 = +bias,relu ; 5 = pairpre dual (blockIdx.z selects W half / output)
template <int EPI>
__global__ void __launch_bounds__(128) k_gemmA(
    const float* __restrict__ X, int KK,
    const float* __restrict__ W, int NOUT,
    const float* __restrict__ bias,
    float* __restrict__ Y, float* __restrict__ Y2) {
  __shared__ float As[2][16][64];
  __shared__ float Bs[2][16][128];
  const int t  = threadIdx.x;
  const int tx = t & 15, ty = t >> 4;
  const int bm0 = blockIdx.x * 64, bn0 = blockIdx.y * 128;
  const int r0 = ty * 8, c0 = tx * 8;
  const int am = t >> 1,  akq = (t & 1) * 8;
  const int bkr = t >> 3, bcq = (t & 7) * 16;

  if (EPI == 5) {
    if (blockIdx.z) { W += (size_t)KK * NOUT; Y = Y2; bias = nullptr; }
  }

  u64 acc[8][4];
  {
    u64 i0 = 0, i1 = 0, i2 = 0, i3 = 0;
    if (EPI != 5 || bias) {
      if (bias) {
        float4 bv0 = *(const float4*)&bias[bn0 + c0];
        float4 bv1 = *(const float4*)&bias[bn0 + c0 + 4];
        i0 = pack2(bv0.x, bv0.y); i1 = pack2(bv0.z, bv0.w);
        i2 = pack2(bv1.x, bv1.y); i3 = pack2(bv1.z, bv1.w);
      }
    }
    #pragma unroll
    for (int i = 0; i < 8; i++) { acc[i][0]=i0; acc[i][1]=i1; acc[i][2]=i2; acc[i][3]=i3; }
  }

  const float* Xp = X + (size_t)(bm0 + am) * KK + akq;
  const float* Wp = W + (size_t)bkr * NOUT + bn0 + bcq;
  const int NT = KK >> 4;

  float4 a0 = *(const float4*)Xp;
  float4 a1 = *(const float4*)(Xp + 4);
  float4 b0 = *(const float4*)Wp;
  float4 b1 = *(const float4*)(Wp + 4);
  float4 b2 = *(const float4*)(Wp + 8);
  float4 b3 = *(const float4*)(Wp + 12);
  {
    As[0][akq + 0][am] = a0.x; As[0][akq + 1][am] = a0.y;
    As[0][akq + 2][am] = a0.z; As[0][akq + 3][am] = a0.w;
    As[0][akq + 4][am] = a1.x; As[0][akq + 5][am] = a1.y;
    As[0][akq + 6][am] = a1.z; As[0][akq + 7][am] = a1.w;
    *(float4*)&Bs[0][bkr][bcq]      = b0;
    *(float4*)&Bs[0][bkr][bcq + 4]  = b1;
    *(float4*)&Bs[0][bkr][bcq + 8]  = b2;
    *(float4*)&Bs[0][bkr][bcq + 12] = b3;
  }
  __syncthreads();

  for (int it = 0; it < NT; it++) {
    const int buf = it & 1;
    if (it + 1 < NT) {
      const float* xp = Xp + (it + 1) * 16;
      a0 = *(const float4*)xp; a1 = *(const float4*)(xp + 4);
      const float* wp = Wp + (size_t)(it + 1) * 16 * NOUT;
      b0 = *(const float4*)wp;        b1 = *(const float4*)(wp + 4);
      b2 = *(const float4*)(wp + 8);  b3 = *(const float4*)(wp + 12);
    }
    #pragma unroll
    for (int k = 0; k < 16; k++) {
      float4 av0 = *(const float4*)&As[buf][k][r0];
      float4 av1 = *(const float4*)&As[buf][k][r0 + 4];
      ulonglong2 bv0 = *(const ulonglong2*)&Bs[buf][k][c0];
      ulonglong2 bv1 = *(const ulonglong2*)&Bs[buf][k][c0 + 4];
      u64 pa[8];
      pa[0] = pack2(av0.x, av0.x); pa[1] = pack2(av0.y, av0.y);
      pa[2] = pack2(av0.z, av0.z); pa[3] = pack2(av0.w, av0.w);
      pa[4] = pack2(av1.x, av1.x); pa[5] = pack2(av1.y, av1.y);
      pa[6] = pack2(av1.z, av1.z); pa[7] = pack2(av1.w, av1.w);
      #pragma unroll
      for (int i = 0; i < 8; i++) {
        ffma2(acc[i][0], pa[i], bv0.x);
        ffma2(acc[i][1], pa[i], bv0.y);
        ffma2(acc[i][2], pa[i], bv1.x);
        ffma2(acc[i][3], pa[i], bv1.y);
      }
    }
    if (it + 1 < NT) {
      const int nb = buf ^ 1;
      As[nb][akq + 0][am] = a0.x; As[nb][akq + 1][am] = a0.y;
      As[nb][akq + 2][am] = a0.z; As[nb][akq + 3][am] = a0.w;
      As[nb][akq + 4][am] = a1.x; As[nb][akq + 5][am] = a1.y;
      As[nb][akq + 6][am] = a1.z; As[nb][akq + 7][am] = a1.w;
      *(float4*)&Bs[nb][bkr][bcq]      = b0;
      *(float4*)&Bs[nb][bkr][bcq + 4]  = b1;
      *(float4*)&Bs[nb][bkr][bcq + 8]  = b2;
      *(float4*)&Bs[nb][bkr][bcq + 12] = b3;
    }
    __syncthreads();
  }

  #pragma unroll
  for (int i = 0; i < 8; i++) {
    float2 u0 = unpack2(acc[i][0]), u1 = unpack2(acc[i][1]);
    float2 u2 = unpack2(acc[i][2]), u3 = unpack2(acc[i][3]);
    float4 f0 = make_float4(u0.x, u0.y, u1.x, u1.y);
    float4 f1 = make_float4(u2.x, u2.y, u3.x, u3.y);
    if (EPI == 1) {
      f0.x = fmaxf(f0.x, 0.f); f0.y = fmaxf(f0.y, 0.f);
      f0.z = fmaxf(f0.z, 0.f); f0.w = fmaxf(f0.w, 0.f);
      f1.x = fmaxf(f1.x, 0.f); f1.y = fmaxf(f1.y, 0.f);
      f1.z = fmaxf(f1.z, 0.f); f1.w = fmaxf(f1.w, 0.f);
    }
    float* yp = &Y[(size_t)(bm0 + r0 + i) * NOUT + bn0 + c0];
    *(float4*)yp       = f0;
    *(float4*)(yp + 4) = f1;
  }
}

// ================ GEMM B: BM=32, BN=128, BK=16, 128 threads, 4x8 tile, fused LN ================
// EPI: 2 = +bias, +res, LN ; 3 = +bias, relu, LN
template <int EPI>
__global__ void __launch_bounds__(128) k_gemmB(
    const float* __restrict__ X, int KK,
    const float* __restrict__ W,
    const float* __restrict__ bias,
    float* __restrict__ Y,
    const float* __restrict__ res,
    const float* __restrict__ g, const float* __restrict__ beta) {
  __shared__ float As[2][16][32];
  __shared__ float Bs[2][16][128];
  const int t  = threadIdx.x;
  const int tx = t & 15, ty = t >> 4;
  const int bm0 = blockIdx.x * 32;
  const int r0 = ty * 4, c0 = tx * 8;
  const int am = t >> 2,  akq = (t & 3) * 4;
  const int bkr = t >> 3, bcq = (t & 7) * 16;

  u64 acc[4][4];
  {
    float4 bv0 = *(const float4*)&bias[c0];
    float4 bv1 = *(const float4*)&bias[c0 + 4];
    u64 i0 = pack2(bv0.x, bv0.y), i1 = pack2(bv0.z, bv0.w);
    u64 i2 = pack2(bv1.x, bv1.y), i3 = pack2(bv1.z, bv1.w);
    #pragma unroll
    for (int i = 0; i < 4; i++) { acc[i][0]=i0; acc[i][1]=i1; acc[i][2]=i2; acc[i][3]=i3; }
  }

  const float* Xp = X + (size_t)(bm0 + am) * KK + akq;
  const float* Wp = W + (size_t)bkr * 128 + bcq;
  const int NT = KK >> 4;

  float4 a0 = *(const float4*)Xp;
  float4 b0 = *(const float4*)Wp;
  float4 b1 = *(const float4*)(Wp + 4);
  float4 b2 = *(const float4*)(Wp + 8);
  float4 b3 = *(const float4*)(Wp + 12);
  {
    As[0][akq + 0][am] = a0.x; As[0][akq + 1][am] = a0.y;
    As[0][akq + 2][am] = a0.z; As[0][akq + 3][am] = a0.w;
    *(float4*)&Bs[0][bkr][bcq]      = b0;
    *(float4*)&Bs[0][bkr][bcq + 4]  = b1;
    *(float4*)&Bs[0][bkr][bcq + 8]  = b2;
    *(float4*)&Bs[0][bkr][bcq + 12] = b3;
  }
  __syncthreads();

  for (int it = 0; it < NT; it++) {
    const int buf = it & 1;
    if (it + 1 < NT) {
      a0 = *(const float4*)(Xp + (it + 1) * 16);
      const float* wp = Wp + (size_t)(it + 1) * 16 * 128;
      b0 = *(const float4*)wp;        b1 = *(const float4*)(wp + 4);
      b2 = *(const float4*)(wp + 8);  b3 = *(const float4*)(wp + 12);
    }
    #pragma unroll
    for (int k = 0; k < 16; k++) {
      float4 av = *(const float4*)&As[buf][k][r0];
      ulonglong2 bv0 = *(const ulonglong2*)&Bs[buf][k][c0];
      ulonglong2 bv1 = *(const ulonglong2*)&Bs[buf][k][c0 + 4];
      u64 pa0 = pack2(av.x, av.x);
      u64 pa1 = pack2(av.y, av.y);
      u64 pa2 = pack2(av.z, av.z);
      u64 pa3 = pack2(av.w, av.w);
      ffma2(acc[0][0], pa0, bv0.x); ffma2(acc[0][1], pa0, bv0.y);
      ffma2(acc[0][2], pa0, bv1.x); ffma2(acc[0][3], pa0, bv1.y);
      ffma2(acc[1][0], pa1, bv0.x); ffma2(acc[1][1], pa1, bv0.y);
      ffma2(acc[1][2], pa1, bv1.x); ffma2(acc[1][3], pa1, bv1.y);
      ffma2(acc[2][0], pa2, bv0.x); ffma2(acc[2][1], pa2, bv0.y);
      ffma2(acc[2][2], pa2, bv1.x); ffma2(acc[2][3], pa2, bv1.y);
      ffma2(acc[3][0], pa3, bv0.x); ffma2(acc[3][1], pa3, bv0.y);
      ffma2(acc[3][2], pa3, bv1.x); ffma2(acc[3][3], pa3, bv1.y);
    }
    if (it + 1 < NT) {
      const int nb = buf ^ 1;
      As[nb][akq + 0][am] = a0.x; As[nb][akq + 1][am] = a0.y;
      As[nb][akq + 2][am] = a0.z; As[nb][akq + 3][am] = a0.w;
      *(float4*)&Bs[nb][bkr][bcq]      = b0;
      *(float4*)&Bs[nb][bkr][bcq + 4]  = b1;
      *(float4*)&Bs[nb][bkr][bcq + 8]  = b2;
      *(float4*)&Bs[nb][bkr][bcq + 12] = b3;
    }
    __syncthreads();
  }

  #pragma unroll
  for (int i = 0; i < 4; i++) {
    const int row = bm0 + r0 + i;
    float f[8];
    #pragma unroll
    for (int j = 0; j < 4; j++) {
      float2 u = unpack2(acc[i][j]);
      f[2 * j] = u.x; f[2 * j + 1] = u.y;
    }
    if (EPI == 3) {
      #pragma unroll
      for (int j = 0; j < 8; j++) f[j] = fmaxf(f[j], 0.f);
    }
    if (EPI == 2) {
      float4 r0v = *(const float4*)&res[(size_t)row * DD + c0];
      float4 r1v = *(const float4*)&res[(size_t)row * DD + c0 + 4];
      f[0] += r0v.x; f[1] += r0v.y; f[2] += r0v.z; f[3] += r0v.w;
      f[4] += r1v.x; f[5] += r1v.y; f[6] += r1v.z; f[7] += r1v.w;
    }
    float s = 0.f, s2 = 0.f;
    #pragma unroll
    for (int j = 0; j < 8; j++) { s += f[j]; s2 += f[j] * f[j]; }
    #pragma unroll
    for (int o = 8; o; o >>= 1) {
      s  += __shfl_xor_sync(0xffffffffu, s,  o);
      s2 += __shfl_xor_sync(0xffffffffu, s2, o);
    }
    float mu = s * (1.f / 128.f);
    float var = s2 * (1.f / 128.f) - mu * mu;
    float rstd = rsqrtf(var + EPSF);
    float4 g0 = *(const float4*)&g[c0];
    float4 g1 = *(const float4*)&g[c0 + 4];
    float4 e0 = *(const float4*)&beta[c0];
    float4 e1 = *(const float4*)&beta[c0 + 4];
    float* yp = &Y[(size_t)row * DD + c0];
    *(float4*)yp = make_float4(
        (f[0] - mu) * rstd * g0.x + e0.x, (f[1] - mu) * rstd * g0.y + e0.y,
        (f[2] - mu) * rstd * g0.z + e0.z, (f[3] - mu) * rstd * g0.w + e0.w);
    *(float4*)(yp + 4) = make_float4(
        (f[4] - mu) * rstd * g1.x + e1.x, (f[5] - mu) * rstd * g1.y + e1.y,
        (f[6] - mu) * rstd * g1.z + e1.z, (f[7] - mu) * rstd * g1.w + e1.w);
  }
}

// ================ attention: split-K partials (SPLITS=2, 128 keys each) ================
__global__ void __launch_bounds__(256) k_attn_part(const float* __restrict__ qkv,
                                                   float* __restrict__ po,
                                                   float* __restrict__ ml) {
  const int split = blockIdx.x, h = blockIdx.y, b = blockIdx.z;
  const int q = threadIdx.x;  // 256
  __shared__ float Ks[128][DHH], Vs[128][DHH];
  const float* base = qkv + (size_t)b * NN * (3 * DD);
  const int hoff = h * DHH;
  const int kbase = split * 128;

  for (int c = threadIdx.x; c < 128 * DHH / 4; c += 256) {
    int r = c >> 3, d4 = (c & 7) << 2;
    *(float4*)&Ks[r][d4] = *(const float4*)&base[(size_t)(kbase + r) * (3 * DD) + DD     + hoff + d4];
    *(float4*)&Vs[r][d4] = *(const float4*)&base[(size_t)(kbase + r) * (3 * DD) + 2 * DD + hoff + d4];
  }
  u64 qp[16];
  {
    const ulonglong2* qptr = (const ulonglong2*)(base + (size_t)q * (3 * DD) + hoff);
    #pragma unroll
    for (int i = 0; i < 8; i++) { ulonglong2 u = qptr[i]; qp[2*i] = u.x; qp[2*i+1] = u.y; }
  }
  __syncthreads();

  float m = -1e30f, l = 0.f;
  u64 op[16];
  #pragma unroll
  for (int i = 0; i < 16; i++) op[i] = 0ull;
  const float scale = 0.17677669529663687f;

  for (int k = 0; k < 128; k++) {
    const ulonglong2* kr = (const ulonglong2*)&Ks[k][0];
    u64 sp0 = 0, sp1 = 0, sp2 = 0, sp3 = 0;
    #pragma unroll
    for (int i = 0; i < 4; i++) {
      ulonglong2 ka = kr[2*i], kb = kr[2*i+1];
      ffma2(sp0, qp[4*i],     ka.x);
      ffma2(sp1, qp[4*i + 1], ka.y);
      ffma2(sp2, qp[4*i + 2], kb.x);
      ffma2(sp3, qp[4*i + 3], kb.y);
    }
    float2 u0 = unpack2(sp0), u1 = unpack2(sp1), u2 = unpack2(sp2), u3 = unpack2(sp3);
    float s = ((u0.x + u0.y) + (u1.x + u1.y)) + ((u2.x + u2.y) + (u3.x + u3.y));
    s *= scale;
    const ulonglong2* vr = (const ulonglong2*)&Vs[k][0];
    if (s > m) {
      float c = __expf(m - s);
      m = s;
      l = l * c + 1.f;
      u64 cp = pack2(c, c);
      #pragma unroll
      for (int i = 0; i < 8; i++) {
        ulonglong2 vv = vr[i];
        op[2*i]     = ffma2_o(op[2*i],     cp, vv.x);
        op[2*i + 1] = ffma2_o(op[2*i + 1], cp, vv.y);
      }
    } else {
      float p = __expf(s - m);
      l += p;
      u64 pp = pack2(p, p);
      #pragma unroll
      for (int i = 0; i < 8; i++) {
        ulonglong2 vv = vr[i];
        ffma2(op[2*i],     pp, vv.x);
        ffma2(op[2*i + 1], pp, vv.y);
      }
    }
  }

  const int bhq = (b * HH + h) * NN + q;
  float* pop = po + ((size_t)split * BHQ + bhq) * 32;
  #pragma unroll
  for (int i = 0; i < 8; i++) {
    float2 a = unpack2(op[2*i]), c = unpack2(op[2*i + 1]);
    *(float4*)&pop[4*i] = make_float4(a.x, a.y, c.x, c.y);
  }
  *(float2*)&ml[((size_t)split * BHQ + bhq) * 2] = make_float2(m, l);
}

__global__ void __launch_bounds__(256) k_attn_comb(const float* __restrict__ po,
                                                   const float* __restrict__ ml,
                                                   float* __restrict__ out) {
  const int tid = blockIdx.x * 256 + threadIdx.x;  // BHQ*8 = 131072
  const int bhq = tid >> 3, dq = (tid & 7) << 2;
  float mv[SPLITS], lv[SPLITS];
  float M = -1e30f;
  #pragma unroll
  for (int s = 0; s < SPLITS; s++) {
    float2 p = *(const float2*)&ml[((size_t)s * BHQ + bhq) * 2];
    mv[s] = p.x; lv[s] = p.y;
    M = fmaxf(M, p.x);
  }
  float w[SPLITS], L = 0.f;
  #pragma unroll
  for (int s = 0; s < SPLITS; s++) { w[s] = __expf(mv[s] - M); L += w[s] * lv[s]; }
  const float inv = 1.f / L;
  float ox = 0.f, oy = 0.f, oz = 0.f, ow = 0.f;
  #pragma unroll
  for (int s = 0; s < SPLITS; s++) {
    float4 p = *(const float4*)&po[((size_t)s * BHQ + bhq) * 32 + dq];
    ox += w[s] * p.x; oy += w[s] * p.y; oz += w[s] * p.z; ow += w[s] * p.w;
  }
  const int b = bhq >> 10, h = (bhq >> 8) & 3, q = bhq & 255;
  *(float4*)&out[(size_t)((b << 8) + q) * DD + h * DHH + dq] =
      make_float4(ox * inv, oy * inv, oz * inv, ow * inv);
}

// ================ pair kernel: 64i x 64j per block, 4x4 pairs per thread ================
#define SP 132  // padded row stride (floats)
__global__ void __launch_bounds__(256) k_pair(const float* __restrict__ w2,
                                              const float* __restrict__ b2,
                                              float* __restrict__ out) {
  extern __shared__ float sm[];
  float* smA = sm;                   // 64*SP
  float* smB = sm + 64 * SP;         // 64*SP
  float* smw = sm + 128 * SP;        // 128
  const int b  = blockIdx.z;
  const int i0 = blockIdx.x * 64;
  const int j0 = blockIdx.y * 64;
  const int t  = threadIdx.x;  // 256
  const int jx = t & 15, iy = t >> 4;

  {
    const float* Ab = g_A  + ((size_t)(b * NN + i0)) * DD;
    const float* Bb = g_Bm + ((size_t)(b * NN + j0)) * DD;
    for (int idx = t; idx < 64 * 32; idx += 256) {
      int r = idx >> 5, dq = (idx & 31) << 2;
      *(float4*)&smA[r * SP + dq] = *(const float4*)&Ab[(size_t)r * DD + dq];
      *(float4*)&smB[r * SP + dq] = *(const float4*)&Bb[(size_t)r * DD + dq];
    }
    if (t < 32) *(float4*)&smw[t * 4] = *(const float4*)&w2[t * 4];
  }
  __syncthreads();

  const int ibl = iy * 4;  // local i base
  u64 acc[4][4];
  #pragma unroll
  for (int ii = 0; ii < 4; ii++)
    #pragma unroll
    for (int jj = 0; jj < 4; jj++) acc[ii][jj] = 0ull;

  for (int d = 0; d < DD; d += 4) {
    ulonglong2 wv = *(const ulonglong2*)&smw[d];
    ulonglong2 av[4], bv[4];
    #pragma unroll
    for (int ii = 0; ii < 4; ii++) av[ii] = *(const ulonglong2*)&smA[(ibl + ii) * SP + d];
    #pragma unroll
    for (int jj = 0; jj < 4; jj++) bv[jj] = *(const ulonglong2*)&smB[(jx + 16 * jj) * SP + d];
    #pragma unroll
    for (int ii = 0; ii < 4; ii++) {
      #pragma unroll
      for (int jj = 0; jj < 4; jj++) {
        u64 s0 = relu2(add2(av[ii].x, bv[jj].x));
        ffma2(acc[ii][jj], s0, wv.x);
        u64 s1 = relu2(add2(av[ii].y, bv[jj].y));
        ffma2(acc[ii][jj], s1, wv.y);
      }
    }
  }

  const float b2v = b2[0];
  float* outb = out + (size_t)b * PP;
  #pragma unroll
  for (int ii = 0; ii < 4; ii++) {
    const int i = i0 + ibl + ii;
    #pragma unroll
    for (int jj = 0; jj < 4; jj++) {
      const int j = j0 + jx + 16 * jj;
      if (j != i) {
        float2 u = unpack2(acc[ii][jj]);
        outb[i * (NN - 1) + j - (j > i ? 1 : 0)] = u.x + u.y + b2v;
      }
    }
  }
}

// ================ host ================
extern "C" void kernel_launch(void* const* d_in, const int* in_sizes, int n_in,
                              void* d_out, int out_size) {
  const float* agents   = (const float*)d_in[0];
  const float* enc_w    = (const float*)d_in[1];
  const float* enc_b    = (const float*)d_in[2];
  const float* enc_g    = (const float*)d_in[3];
  const float* enc_beta = (const float*)d_in[4];
  const float* qkv_w    = (const float*)d_in[5];
  const float* qkv_b    = (const float*)d_in[6];
  const float* attn_ow  = (const float*)d_in[7];
  const float* attn_ob  = (const float*)d_in[8];
  const float* ln1_g    = (const float*)d_in[9];
  const float* ln1_b    = (const float*)d_in[10];
  const float* ffn_w1   = (const float*)d_in[11];
  const float* ffn_b1   = (const float*)d_in[12];
  const float* ffn_w2   = (const float*)d_in[13];
  const float* ffn_b2   = (const float*)d_in[14];
  const float* ln2_g    = (const float*)d_in[15];
  const float* ln2_b    = (const float*)d_in[16];
  const float* rel_w1   = (const float*)d_in[17];
  const float* rel_b1   = (const float*)d_in[18];
  const float* rel_w2   = (const float*)d_in[19];
  const float* rel_b2   = (const float*)d_in[20];
  float* out = (float*)d_out;

  float *px, *pqkv, *pattn, *pffn, *pA, *pBm;
  cudaGetSymbolAddress((void**)&px,    g_x);
  cudaGetSymbolAddress((void**)&pqkv,  g_qkv);
  cudaGetSymbolAddress((void**)&pattn, g_attn);
  cudaGetSymbolAddress((void**)&pffn,  g_ffn);
  cudaGetSymbolAddress((void**)&pA,    g_A);
  cudaGetSymbolAddress((void**)&pBm,   g_Bm);

  const int pair_smem = (128 * SP + 128) * sizeof(float);  // ~68KB
  cudaFuncSetAttribute(k_pair, cudaFuncAttributeMaxDynamicSharedMemorySize, pair_smem);

  // encoder: relu(agents @ enc_w + b) -> LN   (K=64, N=128)
  k_gemmB<3><<<ROWS / 32, 128>>>(agents, FF, enc_w, enc_b, px, nullptr, enc_g, enc_beta);

  for (int l = 0; l < LL; l++) {
    k_gemmA<0><<<dim3(ROWS / 64, 3), 128>>>(px, DD, qkv_w + (size_t)l * DD * 3 * DD,
                                            3 * DD, qkv_b + (size_t)l * 3 * DD, pqkv, nullptr);
    k_attn_part<<<dim3(SPLITS, HH, BB), 256>>>(pqkv, pffn, pA);
    k_attn_comb<<<BHQ * 8 / 256, 256>>>(pffn, pA, pattn);
    k_gemmB<2><<<ROWS / 32, 128>>>(pattn, DD, attn_ow + (size_t)l * DD * DD,
                                   attn_ob + (size_t)l * DD, px, px,
                                   ln1_g + (size_t)l * DD, ln1_b + (size_t)l * DD);
    k_gemmA<1><<<dim3(ROWS / 64, 4), 128>>>(px, DD, ffn_w1 + (size_t)l * DD * DFF_,
                                            DFF_, ffn_b1 + (size_t)l * DFF_, pffn, nullptr);
    k_gemmB<2><<<ROWS / 32, 128>>>(pffn, DFF_, ffn_w2 + (size_t)l * DFF_ * DD,
                                   ffn_b2 + (size_t)l * DD, px, px,
                                   ln2_g + (size_t)l * DD, ln2_b + (size_t)l * DD);
  }

  // pair precompute: A = x@W1[:D]+b1 ; Bm = x@W1[D:]
  k_gemmA<5><<<dim3(ROWS / 64, 1, 2), 128>>>(px, DD, rel_w1, DD, rel_b1, pA, pBm);

  k_pair<<<dim3(NN / 64, NN / 64, BB), 256, pair_smem>>>(rel_w2, rel_b2, out);
}